// round 8
// baseline (speedup 1.0000x reference)
#include <cuda_runtime.h>
#include <cuda_bf16.h>

// Problem shape (fixed by the reference)
#define NWALK 4096
#define NIN   24      // NPART*NDIM
#define HID   256
#define TPW   16      // threads cooperating on one walker
#define BLOCK 128

// Prepped weight storage:
//  gW1t: 6 planes of [HID] float4; plane i4, entry j = W1[4*i4..4*i4+3][j]
//        -> lane handling column j reads 6 float4s at stride 256*16B; within a
//           warp, 16 consecutive j's give one contiguous 256B segment. Coalesced.
//  gP[j] = (b1_j, W2_j, d_j = -2*S_j*W2_j, S_j)
__device__ float4 gW1t[6 * HID];
__device__ float4 gP[HID];

__global__ __launch_bounds__(128)
void prep_kernel(const float* __restrict__ W1,
                 const float* __restrict__ b1,
                 const float* __restrict__ W2)
{
    const int j = blockIdx.x * blockDim.x + threadIdx.x;
    if (j >= HID) return;
    float w[NIN];
    float s = 0.f;
    #pragma unroll
    for (int i = 0; i < NIN; i++) {            // coalesced: consecutive j -> consecutive addr
        w[i] = W1[i * HID + j];
        s = fmaf(w[i], w[i], s);
    }
    #pragma unroll
    for (int i4 = 0; i4 < 6; i4++)             // coalesced float4 stores
        gW1t[i4 * HID + j] = make_float4(w[4*i4], w[4*i4+1], w[4*i4+2], w[4*i4+3]);
    const float w2 = W2[j];
    gP[j] = make_float4(b1[j], w2, -2.f * s * w2, s);
}

__global__ __launch_bounds__(BLOCK)
void kin_kernel(const float* __restrict__ x,
                float* __restrict__ out)
{
    const int gt     = blockIdx.x * BLOCK + threadIdx.x;
    const int walker = gt >> 4;          // / TPW
    const int sub    = gt & (TPW - 1);

    // Load this walker's z (24 floats = 96B, 16B-aligned). 16 lanes broadcast.
    const float4* z4 = reinterpret_cast<const float4*>(x + walker * NIN);
    float zr[NIN];
    #pragma unroll
    for (int c = 0; c < 6; c++) {
        float4 v = z4[c];
        zr[4*c] = v.x; zr[4*c+1] = v.y; zr[4*c+2] = v.z; zr[4*c+3] = v.w;
    }

    float g[NIN];
    #pragma unroll
    for (int i = 0; i < NIN; i++) g[i] = 0.f;
    float lap = 0.f;

    // Each lane handles columns j = jj*16 + sub (lane-interleaved: coalesced LDG.128)
    #pragma unroll 4
    for (int jj = 0; jj < HID / TPW; jj++) {
        const int j = (jj << 4) + sub;

        float w[NIN];
        #pragma unroll
        for (int c = 0; c < 6; c++) {
            float4 v = __ldg(&gW1t[c * HID + j]);
            w[4*c] = v.x; w[4*c+1] = v.y; w[4*c+2] = v.z; w[4*c+3] = v.w;
        }
        const float4 p = __ldg(&gP[j]);        // (b1, W2, d, S)

        // a_j = b1_j + z . W1[:,j]  (4 partial accumulators)
        float a0 = p.x, a1 = 0.f, a2 = 0.f, a3 = 0.f;
        #pragma unroll
        for (int i = 0; i < NIN; i += 4) {
            a0 = fmaf(zr[i],     w[i],     a0);
            a1 = fmaf(zr[i + 1], w[i + 1], a1);
            a2 = fmaf(zr[i + 2], w[i + 2], a2);
            a3 = fmaf(zr[i + 3], w[i + 3], a3);
        }
        const float a = (a0 + a1) + (a2 + a3);

        // tanh(a) = 1 - t, t = 2/(e^{2a}+1); 1-h^2 = t(2-t) (cancellation-free)
        const float e  = __expf(2.f * a);
        const float t  = __fdividef(2.f, e + 1.f);
        const float h  = 1.f - t;
        const float om = t * (2.f - t);        // 1 - h^2
        const float u  = om * p.y;             // tanh'(a) * W2_j

        // laplacian: om*h*(-2 S_j W2_j)
        lap = fmaf(om * h, p.z, lap);

        // gradient accumulation (reuses w[] from registers)
        #pragma unroll
        for (int i = 0; i < NIN; i++) g[i] = fmaf(w[i], u, g[i]);
    }

    // Butterfly reduction across the 16 lanes of this walker
    #pragma unroll
    for (int ofs = 1; ofs < TPW; ofs <<= 1) {
        #pragma unroll
        for (int i = 0; i < NIN; i++)
            g[i] += __shfl_xor_sync(0xffffffffu, g[i], ofs);
        lap += __shfl_xor_sync(0xffffffffu, lap, ofs);
    }

    if (sub == 0) {
        float gsq = 0.f;
        #pragma unroll
        for (int i = 0; i < NIN; i++) gsq = fmaf(g[i], g[i], gsq);
        out[walker] = -0.5f * (lap + gsq);
    }
}

extern "C" void kernel_launch(void* const* d_in, const int* in_sizes, int n_in,
                              void* d_out, int out_size)
{
    // metadata order: x [4096*8*3], W1 [24*256], b1 [256], W2 [256], b2 [1]
    const float* x  = (const float*)d_in[0];
    const float* W1 = (const float*)d_in[1];
    const float* b1 = (const float*)d_in[2];
    const float* W2 = (const float*)d_in[3];
    float* out = (float*)d_out;

    prep_kernel<<<2, 128>>>(W1, b1, W2);
    kin_kernel<<<(NWALK * TPW) / BLOCK, BLOCK>>>(x, out);   // 512 blocks
}